// round 3
// baseline (speedup 1.0000x reference)
#include <cuda_runtime.h>
#include <cuda_bf16.h>
#include <cstdint>

// One warp per edge. Each lane loads one float4 from the source row and one
// from the destination row (32 lanes * 16B = 512B = full 128-float row,
// perfectly coalesced as 4x128B sectors), multiplies, and warp-reduces.
// blockIdx.y selects the edge type:
//   y=0: clicks     (user -> item)
//   y=1: clickedby  (item -> user)
//   y=2: follows    (user -> user)
//
// NOTE: index arrays are int32 on disk (JAX default x64-disabled coerces
// jnp.int64 -> int32).
__global__ __launch_bounds__(256, 8)
void hetero_score_kernel(const float* __restrict__ h_user,
                         const float* __restrict__ h_item,
                         const int* __restrict__ src_clicks,
                         const int* __restrict__ dst_clicks,
                         const int* __restrict__ src_clickedby,
                         const int* __restrict__ dst_clickedby,
                         const int* __restrict__ src_follows,
                         const int* __restrict__ dst_follows,
                         float* __restrict__ out,
                         int E)
{
    const int warp_in_blk = threadIdx.x >> 5;
    const int lane        = threadIdx.x & 31;
    const int e = blockIdx.x * (blockDim.x >> 5) + warp_in_blk;
    if (e >= E) return;

    const int et = blockIdx.y;

    const float* __restrict__ h_src;
    const float* __restrict__ h_dst;
    const int* __restrict__ src;
    const int* __restrict__ dst;

    if (et == 0) {        // clicks: user -> item
        h_src = h_user;  src = src_clicks;
        h_dst = h_item;  dst = dst_clicks;
    } else if (et == 1) { // clickedby: item -> user
        h_src = h_item;  src = src_clickedby;
        h_dst = h_user;  dst = dst_clickedby;
    } else {              // follows: user -> user
        h_src = h_user;  src = src_follows;
        h_dst = h_user;  dst = dst_follows;
    }

    const long long si = (long long)src[e];
    const long long di = (long long)dst[e];

    const float4* __restrict__ a = reinterpret_cast<const float4*>(h_src + si * 128);
    const float4* __restrict__ b = reinterpret_cast<const float4*>(h_dst + di * 128);

    const float4 av = a[lane];
    const float4 bv = b[lane];

    float s = av.x * bv.x;
    s = fmaf(av.y, bv.y, s);
    s = fmaf(av.z, bv.z, s);
    s = fmaf(av.w, bv.w, s);

    // Warp tree reduction over 32 lanes.
    #pragma unroll
    for (int off = 16; off > 0; off >>= 1)
        s += __shfl_xor_sync(0xFFFFFFFFu, s, off);

    if (lane == 0)
        out[(long long)et * E + e] = s;
}

extern "C" void kernel_launch(void* const* d_in, const int* in_sizes, int n_in,
                              void* d_out, int out_size)
{
    const float* h_user        = (const float*)d_in[0];
    const float* h_item        = (const float*)d_in[1];
    const int*   src_clicks    = (const int*)d_in[2];
    const int*   dst_clicks    = (const int*)d_in[3];
    const int*   src_clickedby = (const int*)d_in[4];
    const int*   dst_clickedby = (const int*)d_in[5];
    const int*   src_follows   = (const int*)d_in[6];
    const int*   dst_follows   = (const int*)d_in[7];
    float* out = (float*)d_out;

    const int E = in_sizes[2];           // 500000 edges per etype
    const int warps_per_block = 256 / 32;
    const int blocks_x = (E + warps_per_block - 1) / warps_per_block;

    dim3 grid(blocks_x, 3, 1);
    hetero_score_kernel<<<grid, 256>>>(h_user, h_item,
                                       src_clicks, dst_clicks,
                                       src_clickedby, dst_clickedby,
                                       src_follows, dst_follows,
                                       out, E);
}

// round 4
// speedup vs baseline: 2.2210x; 2.2210x over previous
#include <cuda_runtime.h>
#include <cuda_bf16.h>
#include <cstdint>

// 8 lanes per edge, 4 edges per warp.
// Lane sub (0..7) of edge-group g loads float4 elements {sub, sub+8, sub+16,
// sub+24} of the src row and dst row (each LDG.128 instruction moves 4x128B
// fully-utilized segments, one per edge group). 16 FMAs per lane, then a
// 3-step shuffle reduction over the 8-lane group handles all 4 edges with
// just 3 SHFL instructions per warp.
// blockIdx.y selects edge type:
//   y=0: clicks (user->item), y=1: clickedby (item->user), y=2: follows (user->user)
// Index arrays are int32 (JAX x64-disabled coerces int64 -> int32).
__global__ __launch_bounds__(256)
void hetero_score_kernel(const float* __restrict__ h_user,
                         const float* __restrict__ h_item,
                         const int* __restrict__ src_clicks,
                         const int* __restrict__ dst_clicks,
                         const int* __restrict__ src_clickedby,
                         const int* __restrict__ dst_clickedby,
                         const int* __restrict__ src_follows,
                         const int* __restrict__ dst_follows,
                         float* __restrict__ out,
                         int E)
{
    const int lane = threadIdx.x & 31;
    const int warp = threadIdx.x >> 5;
    const int sub  = lane & 7;          // lane within edge group
    const int grp  = lane >> 3;         // edge group 0..3 within warp

    // 4 edges per warp, 8 warps per block -> 32 edges per block.
    const int e = (blockIdx.x * 8 + warp) * 4 + grp;

    const int et = blockIdx.y;

    const float* __restrict__ h_src;
    const float* __restrict__ h_dst;
    const int* __restrict__ src;
    const int* __restrict__ dst;

    if (et == 0) {        // clicks: user -> item
        h_src = h_user;  src = src_clicks;
        h_dst = h_item;  dst = dst_clicks;
    } else if (et == 1) { // clickedby: item -> user
        h_src = h_item;  src = src_clickedby;
        h_dst = h_user;  dst = dst_clickedby;
    } else {              // follows: user -> user
        h_src = h_user;  src = src_follows;
        h_dst = h_user;  dst = dst_follows;
    }

    float s = 0.0f;

    if (e < E) {
        const long long si = (long long)src[e];
        const long long di = (long long)dst[e];

        const float4* __restrict__ a = reinterpret_cast<const float4*>(h_src + si * 128);
        const float4* __restrict__ b = reinterpret_cast<const float4*>(h_dst + di * 128);

        // Issue all 8 independent loads up front (MLP = 8).
        const float4 a0 = a[sub];
        const float4 a1 = a[sub + 8];
        const float4 a2 = a[sub + 16];
        const float4 a3 = a[sub + 24];
        const float4 b0 = b[sub];
        const float4 b1 = b[sub + 8];
        const float4 b2 = b[sub + 16];
        const float4 b3 = b[sub + 24];

        // Two accumulators for FMA ILP.
        float s0 = a0.x * b0.x;
        float s1 = a1.x * b1.x;
        s0 = fmaf(a0.y, b0.y, s0);
        s1 = fmaf(a1.y, b1.y, s1);
        s0 = fmaf(a0.z, b0.z, s0);
        s1 = fmaf(a1.z, b1.z, s1);
        s0 = fmaf(a0.w, b0.w, s0);
        s1 = fmaf(a1.w, b1.w, s1);
        s0 = fmaf(a2.x, b2.x, s0);
        s1 = fmaf(a3.x, b3.x, s1);
        s0 = fmaf(a2.y, b2.y, s0);
        s1 = fmaf(a3.y, b3.y, s1);
        s0 = fmaf(a2.z, b2.z, s0);
        s1 = fmaf(a3.z, b3.z, s1);
        s0 = fmaf(a2.w, b2.w, s0);
        s1 = fmaf(a3.w, b3.w, s1);
        s = s0 + s1;
    }

    // 3-step butterfly within each 8-lane group; one SHFL instruction per
    // step serves all 4 edges of the warp.
    s += __shfl_xor_sync(0xFFFFFFFFu, s, 4);
    s += __shfl_xor_sync(0xFFFFFFFFu, s, 2);
    s += __shfl_xor_sync(0xFFFFFFFFu, s, 1);

    if (sub == 0 && e < E)
        out[(long long)et * E + e] = s;   // lanes 0,8,16,24 -> 4 consecutive floats
}

extern "C" void kernel_launch(void* const* d_in, const int* in_sizes, int n_in,
                              void* d_out, int out_size)
{
    const float* h_user        = (const float*)d_in[0];
    const float* h_item        = (const float*)d_in[1];
    const int*   src_clicks    = (const int*)d_in[2];
    const int*   dst_clicks    = (const int*)d_in[3];
    const int*   src_clickedby = (const int*)d_in[4];
    const int*   dst_clickedby = (const int*)d_in[5];
    const int*   src_follows   = (const int*)d_in[6];
    const int*   dst_follows   = (const int*)d_in[7];
    float* out = (float*)d_out;

    const int E = in_sizes[2];                 // 500000 edges per etype
    const int edges_per_block = 32;            // 8 warps * 4 edges
    const int blocks_x = (E + edges_per_block - 1) / edges_per_block;

    dim3 grid(blocks_x, 3, 1);
    hetero_score_kernel<<<grid, 256>>>(h_user, h_item,
                                       src_clicks, dst_clicks,
                                       src_clickedby, dst_clickedby,
                                       src_follows, dst_follows,
                                       out, E);
}

// round 8
// speedup vs baseline: 2.2762x; 1.0249x over previous
#include <cuda_runtime.h>
#include <cuda_bf16.h>
#include <cstdint>

// 8 lanes per edge, 4 edges per warp (structure from R4, 98.9us).
// This round: L2 cache-policy steering via createpolicy + cache_hint
// (the direct .L2::evict_last qualifier is rejected by ptxas for widths
// below v8.b32; the cache_hint form works for any width).
//   - table row loads:  ld.global.nc.L2::cache_hint (evict_last policy) —
//     tables ~102MB fit the ~126MB L2; keep them resident.
//   - index loads:      __ldcs (streaming)
//   - output stores:    st.global.cs (streaming)
// blockIdx.y selects edge type:
//   y=0: clicks (user->item), y=1: clickedby (item->user), y=2: follows (user->user)
// Index arrays are int32 (JAX x64-disabled coerces int64 -> int32).

__device__ __forceinline__ uint64_t make_evict_last_policy() {
    uint64_t pol;
    asm("createpolicy.fractional.L2::evict_last.b64 %0, 1.0;" : "=l"(pol));
    return pol;
}

__device__ __forceinline__ float4 ldg_keep(const float4* p, uint64_t pol) {
    float4 v;
    asm volatile("ld.global.nc.L2::cache_hint.v4.f32 {%0,%1,%2,%3}, [%4], %5;"
                 : "=f"(v.x), "=f"(v.y), "=f"(v.z), "=f"(v.w)
                 : "l"(p), "l"(pol));
    return v;
}

__device__ __forceinline__ void stg_stream_f32(float* p, float v) {
    asm volatile("st.global.cs.f32 [%0], %1;" :: "l"(p), "f"(v) : "memory");
}

__global__ __launch_bounds__(256)
void hetero_score_kernel(const float* __restrict__ h_user,
                         const float* __restrict__ h_item,
                         const int* __restrict__ src_clicks,
                         const int* __restrict__ dst_clicks,
                         const int* __restrict__ src_clickedby,
                         const int* __restrict__ dst_clickedby,
                         const int* __restrict__ src_follows,
                         const int* __restrict__ dst_follows,
                         float* __restrict__ out,
                         int E)
{
    const int lane = threadIdx.x & 31;
    const int warp = threadIdx.x >> 5;
    const int sub  = lane & 7;          // lane within edge group
    const int grp  = lane >> 3;         // edge group 0..3 within warp

    const int e = (blockIdx.x * 8 + warp) * 4 + grp;

    const int et = blockIdx.y;

    const float* __restrict__ h_src;
    const float* __restrict__ h_dst;
    const int* __restrict__ src;
    const int* __restrict__ dst;

    if (et == 0) {        // clicks: user -> item
        h_src = h_user;  src = src_clicks;
        h_dst = h_item;  dst = dst_clicks;
    } else if (et == 1) { // clickedby: item -> user
        h_src = h_item;  src = src_clickedby;
        h_dst = h_user;  dst = dst_clickedby;
    } else {              // follows: user -> user
        h_src = h_user;  src = src_follows;
        h_dst = h_user;  dst = dst_follows;
    }

    float s = 0.0f;

    if (e < E) {
        const uint64_t pol = make_evict_last_policy();

        const long long si = (long long)__ldcs(src + e);
        const long long di = (long long)__ldcs(dst + e);

        const float4* a = reinterpret_cast<const float4*>(h_src + si * 128);
        const float4* b = reinterpret_cast<const float4*>(h_dst + di * 128);

        // Issue all 8 independent loads up front (MLP = 8).
        const float4 a0 = ldg_keep(a + sub,      pol);
        const float4 a1 = ldg_keep(a + sub + 8,  pol);
        const float4 a2 = ldg_keep(a + sub + 16, pol);
        const float4 a3 = ldg_keep(a + sub + 24, pol);
        const float4 b0 = ldg_keep(b + sub,      pol);
        const float4 b1 = ldg_keep(b + sub + 8,  pol);
        const float4 b2 = ldg_keep(b + sub + 16, pol);
        const float4 b3 = ldg_keep(b + sub + 24, pol);

        // Two accumulators for FMA ILP.
        float s0 = a0.x * b0.x;
        float s1 = a1.x * b1.x;
        s0 = fmaf(a0.y, b0.y, s0);
        s1 = fmaf(a1.y, b1.y, s1);
        s0 = fmaf(a0.z, b0.z, s0);
        s1 = fmaf(a1.z, b1.z, s1);
        s0 = fmaf(a0.w, b0.w, s0);
        s1 = fmaf(a1.w, b1.w, s1);
        s0 = fmaf(a2.x, b2.x, s0);
        s1 = fmaf(a3.x, b3.x, s1);
        s0 = fmaf(a2.y, b2.y, s0);
        s1 = fmaf(a3.y, b3.y, s1);
        s0 = fmaf(a2.z, b2.z, s0);
        s1 = fmaf(a3.z, b3.z, s1);
        s0 = fmaf(a2.w, b2.w, s0);
        s1 = fmaf(a3.w, b3.w, s1);
        s = s0 + s1;
    }

    // 3-step butterfly within each 8-lane group; one SHFL per step serves
    // all 4 edges of the warp.
    s += __shfl_xor_sync(0xFFFFFFFFu, s, 4);
    s += __shfl_xor_sync(0xFFFFFFFFu, s, 2);
    s += __shfl_xor_sync(0xFFFFFFFFu, s, 1);

    if (sub == 0 && e < E)
        stg_stream_f32(out + (long long)et * E + e, s);
}

extern "C" void kernel_launch(void* const* d_in, const int* in_sizes, int n_in,
                              void* d_out, int out_size)
{
    const float* h_user        = (const float*)d_in[0];
    const float* h_item        = (const float*)d_in[1];
    const int*   src_clicks    = (const int*)d_in[2];
    const int*   dst_clicks    = (const int*)d_in[3];
    const int*   src_clickedby = (const int*)d_in[4];
    const int*   dst_clickedby = (const int*)d_in[5];
    const int*   src_follows   = (const int*)d_in[6];
    const int*   dst_follows   = (const int*)d_in[7];
    float* out = (float*)d_out;

    const int E = in_sizes[2];                 // 500000 edges per etype
    const int edges_per_block = 32;            // 8 warps * 4 edges
    const int blocks_x = (E + edges_per_block - 1) / edges_per_block;

    dim3 grid(blocks_x, 3, 1);
    hetero_score_kernel<<<grid, 256>>>(h_user, h_item,
                                       src_clicks, dst_clicks,
                                       src_clickedby, dst_clickedby,
                                       src_follows, dst_follows,
                                       out, E);
}